// round 9
// baseline (speedup 1.0000x reference)
#include <cuda_runtime.h>

#define NBv   8
#define ND    512
#define NCHv  3
#define NMIXv 4
#define HD    128
#define NTILE 16
#define NHALF 256
#define NARRIVE (NCHv * NTILE)   // 48 tile-combines per batch

typedef unsigned long long u64;

// ---------------- device scratch ----------------
__device__ float  g_part[NBv * NCHv * NTILE * HD];
// partial features: [slot][half][lane] as float4 (m0..m3); slot=(b*3+k)*16+tile
__device__ float4 g_fhalf[NBv * NCHv * NTILE * 2 * 32];
__device__ int    g_tflag[NBv * NCHv * NTILE];   // per-tile arrival (zero-init)
__device__ int    g_cnt[NBv];                     // per-batch combine count
__device__ float  g_sink[512];

// ---------------- f32x2 helpers ----------------
__device__ __forceinline__ u64 fma2(u64 a, u64 b, u64 c) {
    u64 d; asm("fma.rn.f32x2 %0,%1,%2,%3;" : "=l"(d) : "l"(a), "l"(b), "l"(c)); return d;
}
__device__ __forceinline__ u64 add2(u64 a, u64 b) {
    u64 d; asm("add.rn.f32x2 %0,%1,%2;" : "=l"(d) : "l"(a), "l"(b)); return d;
}
__device__ __forceinline__ u64 mul2(u64 a, u64 b) {
    u64 d; asm("mul.rn.f32x2 %0,%1,%2;" : "=l"(d) : "l"(a), "l"(b)); return d;
}
__device__ __forceinline__ u64 pack2(float lo, float hi) {
    u64 d; asm("mov.b64 %0,{%1,%2};" : "=l"(d) : "f"(lo), "f"(hi)); return d;
}
__device__ __forceinline__ void unpack2(float& lo, float& hi, u64 v) {
    asm("mov.b64 {%0,%1},%2;" : "=f"(lo), "=f"(hi) : "l"(v));
}
__device__ __forceinline__ float ex2f(float x) {
    float r; asm("ex2.approx.f32 %0, %1;" : "=f"(r) : "f"(x)); return r;
}

// ---------------- shared-memory overlays ----------------
struct Tables {                    // live during pair loop
    float4 TA[2][NHALF];           // per pair: {u0ma,u0mb,u1ma,u1mb}   8192 B
    float4 TB[2][NHALF];           // per pair: {ca*y,cb*y,sa*y,sb*y}   8192 B
    float4 TP[NHALF];              // {P0,P1,P2,P3}                     4096 B
};                                 // 20480 B
struct Work {                      // live after loop
    float4 red4[8][32];            // [csplit][lane] = 2 pair-float2    4096 B
    float4 sfeat[32];              // combined features
    float  sy2[32];
    float  sred[4][HD];
};
struct TailSm {
    float h1[NCHv * HD];
    float h2[HD];
    float h3[HD];
    float sred[4][HD];
    float out5[NCHv * NMIXv][4];
};

// ---------------- the one kernel ----------------
// grid (33, 3, 8), 512 threads.
//   x < 32            : work block; tile = x>>1, half = x&1 (c in [half*256, +256))
//   x == 32 && k == 0 : tail block for batch b
//   x == 32 && k != 0 : exits
__global__ void __launch_bounds__(512, 4) k_all(
    const float* __restrict__ xc, const float* __restrict__ yc,
    const float* __restrict__ mu, const float* __restrict__ istd,
    const float* __restrict__ w1p, const float* __restrict__ b1p,
    const float* __restrict__ w2, const float* __restrict__ b2,
    const float* __restrict__ w3, const float* __restrict__ b3,
    const float* __restrict__ w4, const float* __restrict__ b4,
    const float* __restrict__ w5, const float* __restrict__ b5,
    float* __restrict__ out)
{
    __shared__ union { Tables t; Work r; TailSm tl; } sm;   // 20480 B
    __shared__ int s_old;

    const int bx = blockIdx.x, k = blockIdx.y, b = blockIdx.z;
    const int tid = threadIdx.x;

    if (bx == 2 * NTILE) {
        // =================== TAIL BLOCK (one per b) ===================
        if (k != 0) return;

        // prefetch layer 2..5 weights while work blocks run
        {
            float4 jk = make_float4(0.f, 0.f, 0.f, 0.f);
            const float4* p2 = (const float4*)w2;
            for (int i = tid; i < 12288; i += 512) {
                const float4 v = p2[i];
                jk.x += v.x; jk.y += v.y; jk.z += v.z; jk.w += v.w;
            }
            const float4* p3 = (const float4*)w3;
            const float4* p4 = (const float4*)w4;
            for (int i = tid; i < 4096; i += 512) {
                const float4 v3 = p3[i], v4 = p4[i];
                jk.x += v3.x + v4.x; jk.y += v3.y + v4.y;
                jk.z += v3.z + v4.z; jk.w += v3.w + v4.w;
            }
            const float4* p5 = (const float4*)w5;
            if (tid < 384) {
                const float4 v = p5[tid];
                jk.x += v.x; jk.y += v.y; jk.z += v.z; jk.w += v.w;
            }
            g_sink[tid] = jk.x + jk.y + jk.z + jk.w;
        }

        if (tid == 0) {
            while (*(volatile int*)&g_cnt[b] != NARRIVE) __nanosleep(128);
        }
        __syncthreads();
        __threadfence();

        const int j = tid & 127, q = tid >> 7;

        if (tid < NCHv * HD) {
            const int kk = tid >> 7, jj = tid & 127;
            const float* p = &g_part[((b * NCHv + kk) * NTILE) * HD + jj];
            float acc = 0.f;
            #pragma unroll
            for (int t = 0; t < NTILE; t++) acc += p[t * HD];
            sm.tl.h1[tid] = acc * (1.0f / 512.0f);
        }
        __syncthreads();

        // layer 2: 384 -> 128
        {
            float acc0 = 0.f, acc1 = 0.f;
            const float4* wr = (const float4*)(w2 + j * (NCHv * HD) + q * 96);
            const float4* xv = (const float4*)(sm.tl.h1 + q * 96);
            #pragma unroll 12
            for (int i = 0; i < 24; i += 2) {
                { const float4 w = wr[i], x = xv[i];
                  acc0 = fmaf(w.x, x.x, acc0); acc0 = fmaf(w.y, x.y, acc0);
                  acc0 = fmaf(w.z, x.z, acc0); acc0 = fmaf(w.w, x.w, acc0); }
                { const float4 w = wr[i+1], x = xv[i+1];
                  acc1 = fmaf(w.x, x.x, acc1); acc1 = fmaf(w.y, x.y, acc1);
                  acc1 = fmaf(w.z, x.z, acc1); acc1 = fmaf(w.w, x.w, acc1); }
            }
            sm.tl.sred[q][j] = acc0 + acc1;
            __syncthreads();
            if (tid < HD)
                sm.tl.h2[tid] = fmaxf(sm.tl.sred[0][tid] + sm.tl.sred[1][tid]
                                      + sm.tl.sred[2][tid] + sm.tl.sred[3][tid]
                                      + b2[tid], 0.f);
            __syncthreads();
        }

        // layer 3
        {
            float acc0 = 0.f;
            const float4* wr = (const float4*)(w3 + j * HD + q * 32);
            const float4* xv = (const float4*)(sm.tl.h2 + q * 32);
            #pragma unroll
            for (int i = 0; i < 8; i++) {
                const float4 w = wr[i], x = xv[i];
                acc0 = fmaf(w.x, x.x, acc0); acc0 = fmaf(w.y, x.y, acc0);
                acc0 = fmaf(w.z, x.z, acc0); acc0 = fmaf(w.w, x.w, acc0);
            }
            sm.tl.sred[q][j] = acc0;
            __syncthreads();
            if (tid < HD)
                sm.tl.h3[tid] = fmaxf(sm.tl.sred[0][tid] + sm.tl.sred[1][tid]
                                      + sm.tl.sred[2][tid] + sm.tl.sred[3][tid]
                                      + b3[tid], 0.f);
            __syncthreads();
        }

        // layer 4
        {
            float acc0 = 0.f;
            const float4* wr = (const float4*)(w4 + j * HD + q * 32);
            const float4* xv = (const float4*)(sm.tl.h3 + q * 32);
            #pragma unroll
            for (int i = 0; i < 8; i++) {
                const float4 w = wr[i], x = xv[i];
                acc0 = fmaf(w.x, x.x, acc0); acc0 = fmaf(w.y, x.y, acc0);
                acc0 = fmaf(w.z, x.z, acc0); acc0 = fmaf(w.w, x.w, acc0);
            }
            sm.tl.sred[q][j] = acc0;
            __syncthreads();
            if (tid < HD)
                sm.tl.h2[tid] = fmaxf(sm.tl.sred[0][tid] + sm.tl.sred[1][tid]
                                      + sm.tl.sred[2][tid] + sm.tl.sred[3][tid]
                                      + b4[tid], 0.f);
            __syncthreads();
        }

        // layer 5
        if (tid < NCHv * NMIXv * 4) {
            const int j5 = tid >> 2, p = tid & 3;
            float acc = 0.f;
            const float4* wr = (const float4*)(w5 + j5 * HD + p * 32);
            const float4* xv = (const float4*)(sm.tl.h2 + p * 32);
            #pragma unroll
            for (int i = 0; i < 8; i++) {
                const float4 w = wr[i], x = xv[i];
                acc = fmaf(w.x, x.x, acc); acc = fmaf(w.y, x.y, acc);
                acc = fmaf(w.z, x.z, acc); acc = fmaf(w.w, x.w, acc);
            }
            sm.tl.out5[j5][p] = acc;
        }
        __syncthreads();
        if (tid < NCHv * NMIXv)
            out[b * (NCHv * NMIXv) + tid] =
                sm.tl.out5[tid][0] + sm.tl.out5[tid][1] + sm.tl.out5[tid][2]
                + sm.tl.out5[tid][3] + b5[tid];

        __syncthreads();
        if (tid == 0) g_cnt[b] = 0;
        return;
    }

    // =================== WORK BLOCK ===================
    const int tile = bx >> 1, half = bx & 1;
    const int slot = (b * NCHv + k) * NTILE + tile;
    const float PI2   = 6.2831853071795864f;
    const float ALPHA = 5.3364454f;   // 2pi*sqrt(0.5*log2(e))

    // ---- build half c-table: thread t -> (c = t>>1, pair = t&1) ----
    {
        const int cl = tid >> 1;          // 0..255
        const int pr = tid & 1;           // mix pair
        const int c  = half * NHALF + cl;
        const float x0 = xc[((b * ND + c) * 2 + 0) * NCHv + k];
        const float x1 = xc[((b * ND + c) * 2 + 1) * NCHv + k];
        const float y  = yc[(b * ND + c) * NCHv + k];
        float U0[2], U1[2], CO[2], SI[2], P[2];
        #pragma unroll
        for (int mm = 0; mm < 2; mm++) {
            const int m = pr * 2 + mm;
            const float u0 = x0 * istd[2 * m + 0] * ALPHA;
            const float u1 = x1 * istd[2 * m + 1] * ALPHA;
            float t = fmaf(x0, mu[2 * m + 0], x1 * mu[2 * m + 1]);
            t -= rintf(t);
            float sn, cn; __sincosf(PI2 * t, &sn, &cn);
            U0[mm] = u0; U1[mm] = u1; CO[mm] = cn * y; SI[mm] = sn * y;
            P[mm] = -fmaf(u0, u0, u1 * u1);
        }
        sm.t.TA[pr][cl] = make_float4(U0[0], U0[1], U1[0], U1[1]);
        sm.t.TB[pr][cl] = make_float4(CO[0], CO[1], SI[0], SI[1]);
        *((float2*)&sm.t.TP[cl] + pr) = make_float2(P[0], P[1]);
    }

    // ---- per-warp a-side: warp w -> pair p = w&1, csplit cs = w>>1 ----
    const int al = tid & 31;
    const int w  = tid >> 5;
    const int p  = w & 1;
    const int cs = w >> 1;            // 0..7
    const int a  = tile * 32 + al;

    u64 a0, a1, ca, sa, pa;
    {
        const float x0 = xc[((b * ND + a) * 2 + 0) * NCHv + k];
        const float x1 = xc[((b * ND + a) * 2 + 1) * NCHv + k];
        float U0[2], U1[2], CO[2], SI[2], P[2];
        #pragma unroll
        for (int mm = 0; mm < 2; mm++) {
            const int m = p * 2 + mm;
            const float u0 = x0 * istd[2 * m + 0] * ALPHA;
            const float u1 = x1 * istd[2 * m + 1] * ALPHA;
            float t = fmaf(x0, mu[2 * m + 0], x1 * mu[2 * m + 1]);
            t -= rintf(t);
            float sn, cn; __sincosf(PI2 * t, &sn, &cn);
            U0[mm] = 2.0f * u0; U1[mm] = 2.0f * u1; CO[mm] = cn; SI[mm] = sn;
            P[mm] = -fmaf(u0, u0, u1 * u1);
        }
        a0 = pack2(U0[0], U0[1]);
        a1 = pack2(U1[0], U1[1]);
        ca = pack2(CO[0], CO[1]);
        sa = pack2(SI[0], SI[1]);
        pa = pack2(P[0],  P[1]);
    }
    __syncthreads();

    // ---- pair loop: 32 iters over this half's 256 c, 2 mixes per warp ----
    const float4* __restrict__ TAp = sm.t.TA[p];
    const float4* __restrict__ TBp = sm.t.TB[p];
    u64 acc = 0;

    #pragma unroll 4
    for (int c = cs; c < NHALF; c += 8) {
        const float4 A = TAp[c];
        const float4 B = TBp[c];
        const float2 Pc = *((const float2*)&sm.t.TP[c] + p);
        u64 s = add2(pa, pack2(Pc.x, Pc.y));
        s = fma2(pack2(A.x, A.y), a0, s);
        s = fma2(pack2(A.z, A.w), a1, s);
        u64 cvy = mul2(pack2(B.z, B.w), sa);
        cvy = fma2(pack2(B.x, B.y), ca, cvy);
        float s0, s1; unpack2(s0, s1, s);
        acc = fma2(pack2(ex2f(s0), ex2f(s1)), cvy, acc);
    }

    __syncthreads();   // tables dead; Work aliases them
    {
        float lo, hi; unpack2(lo, hi, acc);
        *((float2*)&sm.r.red4[cs][al] + p) = make_float2(lo, hi);
    }
    __syncthreads();

    // ---- reduce 8 c-splits; write partial feature half to gmem ----
    if (tid < 64) {
        const int lane = tid >> 1, pp = tid & 1;
        u64 f = 0;
        #pragma unroll
        for (int s = 0; s < 8; s++)
            f = add2(f, *(const u64*)((const char*)&sm.r.red4[s][lane] + 8 * pp));
        float lo, hi; unpack2(lo, hi, f);
        *((float2*)&g_fhalf[(slot * 2 + half) * 32 + lane] + pp) = make_float2(lo, hi);
    }

    // ---- publish, then per-tile arrival; second arriver combines ----
    __threadfence();
    __syncthreads();
    if (tid == 0) s_old = atomicAdd(&g_tflag[slot], 1);
    __syncthreads();
    if (s_old == 0) return;
    __threadfence();   // acquire: see the other half's g_fhalf

    // ---- combine halves + zitter ----
    if (tid < 32) {
        const float4 f0 = g_fhalf[(slot * 2 + 0) * 32 + tid];
        const float4 f1 = g_fhalf[(slot * 2 + 1) * 32 + tid];
        const float y = yc[(b * ND + tile * 32 + tid) * NCHv + k];
        const float zy = 1.0e-4f * y;
        sm.r.sfeat[tid] = make_float4(f0.x + f1.x + zy, f0.y + f1.y + zy,
                                      f0.z + f1.z + zy, f0.w + f1.w + zy);
        sm.r.sy2[tid] = y;
    }
    __syncthreads();
    if (tid == 0) g_tflag[slot] = 0;   // reset for next replay (after reads)

    // ---- fused layer 1 on this tile's 32 a's ----
    {
        const int j = tid & 127, q = tid >> 7;
        const float wv0 = w1p[j * 5 + 0], wv1 = w1p[j * 5 + 1], wv2 = w1p[j * 5 + 2];
        const float wv3 = w1p[j * 5 + 3], wv4 = w1p[j * 5 + 4], bb = b1p[j];
        float acc1 = 0.f;
        #pragma unroll
        for (int aa = 0; aa < 8; aa++) {
            const int lane = q * 8 + aa;
            const float4 f = sm.r.sfeat[lane];
            const float y = sm.r.sy2[lane];
            float h = fmaf(wv0, f.x, bb);
            h = fmaf(wv1, f.y, h);
            h = fmaf(wv2, f.z, h);
            h = fmaf(wv3, f.w, h);
            h = fmaf(wv4, y, h);
            acc1 += fmaxf(h, 0.f);
        }
        sm.r.sred[q][j] = acc1;
    }
    __syncthreads();
    if (tid < HD) {
        g_part[slot * HD + tid] =
            sm.r.sred[0][tid] + sm.r.sred[1][tid] + sm.r.sred[2][tid] + sm.r.sred[3][tid];
    }

    __threadfence();
    __syncthreads();
    if (tid == 0) atomicAdd(&g_cnt[b], 1);
}

// ---------------- launch ----------------
extern "C" void kernel_launch(void* const* d_in, const int* in_sizes, int n_in,
                              void* d_out, int out_size)
{
    const float* xc   = (const float*)d_in[0];
    const float* yc   = (const float*)d_in[1];
    const float* mu   = (const float*)d_in[2];
    const float* istd = (const float*)d_in[3];
    const float* w1   = (const float*)d_in[4];
    const float* b1   = (const float*)d_in[5];
    const float* w2   = (const float*)d_in[6];
    const float* b2   = (const float*)d_in[7];
    const float* w3   = (const float*)d_in[8];
    const float* b3   = (const float*)d_in[9];
    const float* w4   = (const float*)d_in[10];
    const float* b4   = (const float*)d_in[11];
    const float* w5   = (const float*)d_in[12];
    const float* b5   = (const float*)d_in[13];
    float* out = (float*)d_out;

    dim3 g1(2 * NTILE + 1, NCHv, NBv);   // 33 x 3 x 8 = 792 blocks
    k_all<<<g1, 512>>>(xc, yc, mu, istd, w1, b1,
                       w2, b2, w3, b3, w4, b4, w5, b5, out);
}

// round 10
// speedup vs baseline: 1.0008x; 1.0008x over previous
#include <cuda_runtime.h>

#define NBv   8
#define ND    512
#define NCHv  3
#define NMIXv 4
#define HD    128
#define NTILE 16
#define NHALF 256
#define NARRIVE (NCHv * NTILE)   // 48 tile-combines per batch

typedef unsigned long long u64;

// ---------------- device scratch ----------------
__device__ float  g_part[NBv * NCHv * NTILE * HD];
__device__ float4 g_fhalf[NBv * NCHv * NTILE * 2 * 32]; // [slot][half][lane] m0..m3
__device__ int    g_tflag[NBv * NCHv * NTILE];          // per-tile arrival (zero-init)
__device__ int    g_cnt[NBv];                            // per-batch combine count
__device__ float  g_sink[256];

// ---------------- f32x2 helpers ----------------
__device__ __forceinline__ u64 fma2(u64 a, u64 b, u64 c) {
    u64 d; asm("fma.rn.f32x2 %0,%1,%2,%3;" : "=l"(d) : "l"(a), "l"(b), "l"(c)); return d;
}
__device__ __forceinline__ u64 add2(u64 a, u64 b) {
    u64 d; asm("add.rn.f32x2 %0,%1,%2;" : "=l"(d) : "l"(a), "l"(b)); return d;
}
__device__ __forceinline__ u64 mul2(u64 a, u64 b) {
    u64 d; asm("mul.rn.f32x2 %0,%1,%2;" : "=l"(d) : "l"(a), "l"(b)); return d;
}
__device__ __forceinline__ u64 pack2(float lo, float hi) {
    u64 d; asm("mov.b64 %0,{%1,%2};" : "=l"(d) : "f"(lo), "f"(hi)); return d;
}
__device__ __forceinline__ void unpack2(float& lo, float& hi, u64 v) {
    asm("mov.b64 {%0,%1},%2;" : "=f"(lo), "=f"(hi) : "l"(v));
}
__device__ __forceinline__ float ex2f(float x) {
    float r; asm("ex2.approx.f32 %0, %1;" : "=f"(r) : "f"(x)); return r;
}

// ---------------- shared-memory overlays ----------------
struct Tables {                       // live during pair loop
    float4 A[NHALF];   // {u0m0, u0m1, u1m0, u1m1}
    float4 B[NHALF];   // {c0*y, c1*y, s0*y, s1*y}
    float4 C[NHALF];   // mixes 2,3 u's
    float4 D[NHALF];   // mixes 2,3 c*y / s*y
    float4 P[NHALF];   // {P0,P1,P2,P3}
};                                    // 20480 B
struct Work {                         // live after loop
    u64    red[8][32][2];             // 4096 B
    float4 sfeat[32];                 // combined features
    float  sy2[32];
    float  sred[2][HD];               // 1024 B
};
struct TailSm {
    float h1[NCHv * HD];
    float h2[HD];
    float h3[HD];
    float sred[2][HD];
    float out5[NCHv * NMIXv][4];
};

// ---------------- the one kernel ----------------
// grid (33, 3, 8), 256 threads.
//   x < 32            : work block; tile = x>>1, half = x&1
//   x == 32 && k == 0 : tail block for batch b
//   x == 32 && k != 0 : exits
__global__ void __launch_bounds__(256, 3) k_all(
    const float* __restrict__ xc, const float* __restrict__ yc,
    const float* __restrict__ mu, const float* __restrict__ istd,
    const float* __restrict__ w1p, const float* __restrict__ b1p,
    const float* __restrict__ w2, const float* __restrict__ b2,
    const float* __restrict__ w3, const float* __restrict__ b3,
    const float* __restrict__ w4, const float* __restrict__ b4,
    const float* __restrict__ w5, const float* __restrict__ b5,
    float* __restrict__ out)
{
    __shared__ union { Tables t; Work r; TailSm tl; } sm;   // 20480 B
    __shared__ int s_old;

    const int bx = blockIdx.x, k = blockIdx.y, b = blockIdx.z;
    const int tid = threadIdx.x;

    if (bx == 2 * NTILE) {
        // =================== TAIL BLOCK (one per b) ===================
        if (k != 0) return;

        // prefetch layer 2..5 weights while work blocks run
        {
            float4 jk = make_float4(0.f, 0.f, 0.f, 0.f);
            const float4* p2 = (const float4*)w2;
            for (int i = tid; i < 12288; i += 256) {
                const float4 v = p2[i];
                jk.x += v.x; jk.y += v.y; jk.z += v.z; jk.w += v.w;
            }
            const float4* p3 = (const float4*)w3;
            const float4* p4 = (const float4*)w4;
            for (int i = tid; i < 4096; i += 256) {
                const float4 v3 = p3[i], v4 = p4[i];
                jk.x += v3.x + v4.x; jk.y += v3.y + v4.y;
                jk.z += v3.z + v4.z; jk.w += v3.w + v4.w;
            }
            const float4* p5 = (const float4*)w5;
            for (int i = tid; i < 384; i += 256) {
                const float4 v = p5[i];
                jk.x += v.x; jk.y += v.y; jk.z += v.z; jk.w += v.w;
            }
            g_sink[tid] = jk.x + jk.y + jk.z + jk.w;
        }

        if (tid == 0) {
            while (*(volatile int*)&g_cnt[b] != NARRIVE) __nanosleep(128);
        }
        __syncthreads();
        __threadfence();

        const int j = tid & 127, q = tid >> 7;   // q in {0,1}

        // reduce 16 tile-partials per (k,j) -> h1 (mean over 512 a)
        for (int i = tid; i < NCHv * HD; i += 256) {
            const int kk = i >> 7, jj = i & 127;
            const float* p = &g_part[((b * NCHv + kk) * NTILE) * HD + jj];
            float acc = 0.f;
            #pragma unroll
            for (int t = 0; t < NTILE; t++) acc += p[t * HD];
            sm.tl.h1[i] = acc * (1.0f / 512.0f);
        }
        __syncthreads();

        // layer 2: 384 -> 128, q splits input into 192+192
        {
            float acc0 = 0.f, acc1 = 0.f;
            const float4* wr = (const float4*)(w2 + j * (NCHv * HD) + q * 192);
            const float4* xv = (const float4*)(sm.tl.h1 + q * 192);
            #pragma unroll 12
            for (int i = 0; i < 48; i += 2) {
                { const float4 w = wr[i], x = xv[i];
                  acc0 = fmaf(w.x, x.x, acc0); acc0 = fmaf(w.y, x.y, acc0);
                  acc0 = fmaf(w.z, x.z, acc0); acc0 = fmaf(w.w, x.w, acc0); }
                { const float4 w = wr[i+1], x = xv[i+1];
                  acc1 = fmaf(w.x, x.x, acc1); acc1 = fmaf(w.y, x.y, acc1);
                  acc1 = fmaf(w.z, x.z, acc1); acc1 = fmaf(w.w, x.w, acc1); }
            }
            sm.tl.sred[q][j] = acc0 + acc1;
            __syncthreads();
            if (tid < HD)
                sm.tl.h2[tid] = fmaxf(sm.tl.sred[0][tid] + sm.tl.sred[1][tid]
                                      + b2[tid], 0.f);
            __syncthreads();
        }

        // layer 3: 128 -> 128, q splits into 64+64
        {
            float acc0 = 0.f;
            const float4* wr = (const float4*)(w3 + j * HD + q * 64);
            const float4* xv = (const float4*)(sm.tl.h2 + q * 64);
            #pragma unroll
            for (int i = 0; i < 16; i++) {
                const float4 w = wr[i], x = xv[i];
                acc0 = fmaf(w.x, x.x, acc0); acc0 = fmaf(w.y, x.y, acc0);
                acc0 = fmaf(w.z, x.z, acc0); acc0 = fmaf(w.w, x.w, acc0);
            }
            sm.tl.sred[q][j] = acc0;
            __syncthreads();
            if (tid < HD)
                sm.tl.h3[tid] = fmaxf(sm.tl.sred[0][tid] + sm.tl.sred[1][tid]
                                      + b3[tid], 0.f);
            __syncthreads();
        }

        // layer 4: 128 -> 128 (into h2)
        {
            float acc0 = 0.f;
            const float4* wr = (const float4*)(w4 + j * HD + q * 64);
            const float4* xv = (const float4*)(sm.tl.h3 + q * 64);
            #pragma unroll
            for (int i = 0; i < 16; i++) {
                const float4 w = wr[i], x = xv[i];
                acc0 = fmaf(w.x, x.x, acc0); acc0 = fmaf(w.y, x.y, acc0);
                acc0 = fmaf(w.z, x.z, acc0); acc0 = fmaf(w.w, x.w, acc0);
            }
            sm.tl.sred[q][j] = acc0;
            __syncthreads();
            if (tid < HD)
                sm.tl.h2[tid] = fmaxf(sm.tl.sred[0][tid] + sm.tl.sred[1][tid]
                                      + b4[tid], 0.f);
            __syncthreads();
        }

        // layer 5: 128 -> 12
        if (tid < NCHv * NMIXv * 4) {
            const int j5 = tid >> 2, p = tid & 3;
            float acc = 0.f;
            const float4* wr = (const float4*)(w5 + j5 * HD + p * 32);
            const float4* xv = (const float4*)(sm.tl.h2 + p * 32);
            #pragma unroll
            for (int i = 0; i < 8; i++) {
                const float4 w = wr[i], x = xv[i];
                acc = fmaf(w.x, x.x, acc); acc = fmaf(w.y, x.y, acc);
                acc = fmaf(w.z, x.z, acc); acc = fmaf(w.w, x.w, acc);
            }
            sm.tl.out5[j5][p] = acc;
        }
        __syncthreads();
        if (tid < NCHv * NMIXv)
            out[b * (NCHv * NMIXv) + tid] =
                sm.tl.out5[tid][0] + sm.tl.out5[tid][1] + sm.tl.out5[tid][2]
                + sm.tl.out5[tid][3] + b5[tid];

        __syncthreads();
        if (tid == 0) g_cnt[b] = 0;
        return;
    }

    // =================== WORK BLOCK (256 threads, 85-reg budget) ===========
    const int tile = bx >> 1, half = bx & 1;
    const int slot = (b * NCHv + k) * NTILE + tile;
    const float PI2   = 6.2831853071795864f;
    const float ALPHA = 5.3364454f;   // 2pi*sqrt(0.5*log2(e))

    // ---- build half c-table (one point per thread), y folded into cos/sin ----
    {
        const int cl = tid;                       // 0..255
        const int c  = half * NHALF + cl;
        const float x0 = xc[((b * ND + c) * 2 + 0) * NCHv + k];
        const float x1 = xc[((b * ND + c) * 2 + 1) * NCHv + k];
        const float y  = yc[(b * ND + c) * NCHv + k];
        float U0[4], U1[4], CO[4], SI[4], P[4];
        #pragma unroll
        for (int m = 0; m < NMIXv; m++) {
            const float u0 = x0 * istd[2 * m + 0] * ALPHA;
            const float u1 = x1 * istd[2 * m + 1] * ALPHA;
            float t = fmaf(x0, mu[2 * m + 0], x1 * mu[2 * m + 1]);
            t -= rintf(t);
            float sn, cn; __sincosf(PI2 * t, &sn, &cn);
            U0[m] = u0; U1[m] = u1; CO[m] = cn * y; SI[m] = sn * y;
            P[m] = -fmaf(u0, u0, u1 * u1);
        }
        sm.t.A[cl] = make_float4(U0[0], U0[1], U1[0], U1[1]);
        sm.t.B[cl] = make_float4(CO[0], CO[1], SI[0], SI[1]);
        sm.t.C[cl] = make_float4(U0[2], U0[3], U1[2], U1[3]);
        sm.t.D[cl] = make_float4(CO[2], CO[3], SI[2], SI[3]);
        sm.t.P[cl] = make_float4(P[0], P[1], P[2], P[3]);
    }

    // ---- per-lane A-side values ----
    const int al = tid & 31;
    const int cs = tid >> 5;          // c-split 0..7, uniform per warp
    const int a  = tile * 32 + al;

    u64 a0[2], a1[2], ca[2], sa[2], pa[2];
    {
        const float x0 = xc[((b * ND + a) * 2 + 0) * NCHv + k];
        const float x1 = xc[((b * ND + a) * 2 + 1) * NCHv + k];
        float U0[4], U1[4], CO[4], SI[4], P[4];
        #pragma unroll
        for (int m = 0; m < NMIXv; m++) {
            const float u0 = x0 * istd[2 * m + 0] * ALPHA;
            const float u1 = x1 * istd[2 * m + 1] * ALPHA;
            float t = fmaf(x0, mu[2 * m + 0], x1 * mu[2 * m + 1]);
            t -= rintf(t);
            float sn, cn; __sincosf(PI2 * t, &sn, &cn);
            U0[m] = 2.0f * u0; U1[m] = 2.0f * u1; CO[m] = cn; SI[m] = sn;
            P[m] = -fmaf(u0, u0, u1 * u1);
        }
        #pragma unroll
        for (int p = 0; p < 2; p++) {
            a0[p] = pack2(U0[2*p], U0[2*p+1]);
            a1[p] = pack2(U1[2*p], U1[2*p+1]);
            ca[p] = pack2(CO[2*p], CO[2*p+1]);
            sa[p] = pack2(SI[2*p], SI[2*p+1]);
            pa[p] = pack2(P[2*p],  P[2*p+1]);
        }
    }
    __syncthreads();

    // ---- pair loop: warp = 32 a-lanes, 8 c-splits, 32 iters ----
    u64 acc0 = 0, acc1 = 0;

    #pragma unroll 4
    for (int c = cs; c < NHALF; c += 8) {
        const float4 A = sm.t.A[c];
        const float4 B = sm.t.B[c];
        const float4 C = sm.t.C[c];
        const float4 D = sm.t.D[c];
        const float4 P = sm.t.P[c];
        // mix pair 0
        {
            u64 s = add2(pa[0], pack2(P.x, P.y));
            s = fma2(pack2(A.x, A.y), a0[0], s);
            s = fma2(pack2(A.z, A.w), a1[0], s);
            u64 cvy = mul2(pack2(B.z, B.w), sa[0]);
            cvy = fma2(pack2(B.x, B.y), ca[0], cvy);
            float s0, s1; unpack2(s0, s1, s);
            acc0 = fma2(pack2(ex2f(s0), ex2f(s1)), cvy, acc0);
        }
        // mix pair 1
        {
            u64 s = add2(pa[1], pack2(P.z, P.w));
            s = fma2(pack2(C.x, C.y), a0[1], s);
            s = fma2(pack2(C.z, C.w), a1[1], s);
            u64 cvy = mul2(pack2(D.z, D.w), sa[1]);
            cvy = fma2(pack2(D.x, D.y), ca[1], cvy);
            float s0, s1; unpack2(s0, s1, s);
            acc1 = fma2(pack2(ex2f(s0), ex2f(s1)), cvy, acc1);
        }
    }

    __syncthreads();   // tables dead; Work aliases them
    sm.r.red[cs][al][0] = acc0;
    sm.r.red[cs][al][1] = acc1;
    __syncthreads();

    // ---- reduce 8 c-splits; write partial feature half to gmem ----
    if (tid < 64) {
        const int lane = tid >> 1, pp = tid & 1;
        u64 f = sm.r.red[0][lane][pp];
        #pragma unroll
        for (int s = 1; s < 8; s++) f = add2(f, sm.r.red[s][lane][pp]);
        float lo, hi; unpack2(lo, hi, f);
        *((float2*)&g_fhalf[(slot * 2 + half) * 32 + lane] + pp) = make_float2(lo, hi);
    }

    // ---- publish, then per-tile arrival; second arriver combines ----
    __threadfence();
    __syncthreads();
    if (tid == 0) s_old = atomicAdd(&g_tflag[slot], 1);
    __syncthreads();
    if (s_old == 0) return;
    __threadfence();   // acquire: see the other half's g_fhalf

    // ---- combine halves + zitter ----
    if (tid < 32) {
        const float4 f0 = g_fhalf[(slot * 2 + 0) * 32 + tid];
        const float4 f1 = g_fhalf[(slot * 2 + 1) * 32 + tid];
        const float y = yc[(b * ND + tile * 32 + tid) * NCHv + k];
        const float zy = 1.0e-4f * y;
        sm.r.sfeat[tid] = make_float4(f0.x + f1.x + zy, f0.y + f1.y + zy,
                                      f0.z + f1.z + zy, f0.w + f1.w + zy);
        sm.r.sy2[tid] = y;
    }
    __syncthreads();
    if (tid == 0) g_tflag[slot] = 0;   // reset for next replay (after reads)

    // ---- fused layer 1 on this tile's 32 a's ----
    {
        const int j = tid & 127, q = tid >> 7;   // q in {0,1}, 16 a's each
        const float wv0 = w1p[j * 5 + 0], wv1 = w1p[j * 5 + 1], wv2 = w1p[j * 5 + 2];
        const float wv3 = w1p[j * 5 + 3], wv4 = w1p[j * 5 + 4], bb = b1p[j];
        float acc = 0.f;
        #pragma unroll
        for (int aa = 0; aa < 16; aa++) {
            const int lane = q * 16 + aa;
            const float4 f = sm.r.sfeat[lane];
            const float y = sm.r.sy2[lane];
            float h = fmaf(wv0, f.x, bb);
            h = fmaf(wv1, f.y, h);
            h = fmaf(wv2, f.z, h);
            h = fmaf(wv3, f.w, h);
            h = fmaf(wv4, y, h);
            acc += fmaxf(h, 0.f);
        }
        sm.r.sred[q][j] = acc;
    }
    __syncthreads();
    if (tid < HD) {
        g_part[slot * HD + tid] = sm.r.sred[0][tid] + sm.r.sred[1][tid];
    }

    __threadfence();
    __syncthreads();
    if (tid == 0) atomicAdd(&g_cnt[b], 1);
}

// ---------------- launch ----------------
extern "C" void kernel_launch(void* const* d_in, const int* in_sizes, int n_in,
                              void* d_out, int out_size)
{
    const float* xc   = (const float*)d_in[0];
    const float* yc   = (const float*)d_in[1];
    const float* mu   = (const float*)d_in[2];
    const float* istd = (const float*)d_in[3];
    const float* w1   = (const float*)d_in[4];
    const float* b1   = (const float*)d_in[5];
    const float* w2   = (const float*)d_in[6];
    const float* b2   = (const float*)d_in[7];
    const float* w3   = (const float*)d_in[8];
    const float* b3   = (const float*)d_in[9];
    const float* w4   = (const float*)d_in[10];
    const float* b4   = (const float*)d_in[11];
    const float* w5   = (const float*)d_in[12];
    const float* b5   = (const float*)d_in[13];
    float* out = (float*)d_out;

    dim3 g1(2 * NTILE + 1, NCHv, NBv);   // 33 x 3 x 8 = 792 blocks, 256 threads
    k_all<<<g1, 256>>>(xc, yc, mu, istd, w1, b1,
                       w2, b2, w3, b3, w4, b4, w5, b5, out);
}

// round 11
// speedup vs baseline: 1.1802x; 1.1793x over previous
#include <cuda_runtime.h>

#define NBv   8
#define ND    512
#define NCHv  3
#define NMIXv 4
#define HD    128
#define NTILE 16

// ---------------- device scratch ----------------
__device__ float g_part[NBv * NCHv * NTILE * HD];  // per-(b,k,tile) layer1 partials

__device__ __forceinline__ float ex2f(float x) {
    float r; asm("ex2.approx.f32 %0, %1;" : "=f"(r) : "f"(x)); return r;
}

// ---------------- shared-memory overlays ----------------
struct Tables {
    float4 A[ND];   // {u0m0, u0m1, u1m0, u1m1}
    float4 B[ND];   // {c0*y, c1*y, s0*y, s1*y}
    float4 C[ND];   // mixes 2,3 u's
    float4 D[ND];   // mixes 2,3 c*y / s*y
    float4 P[ND];   // {P0,P1,P2,P3}
};                                    // 40960 B
struct Reduce {
    float red[8][32][4];              // 4096 B  [csplit][lane][mix]
    float sred[2][HD];                // 1024 B
};

// ---------------- kernel 1: pair + fused layer 1 ----------------
// grid (16, 3, 8), 256 threads (8 warps: warp = 32 a-lanes x c-split).
//   exp arg: -(|ua-uc|^2) = Pa + Pc + (2u0a)*u0c + (2u1a)*u1c
//   K*y: ex2(s) * (ca*(cc*y) + sa*(sc*y))
__global__ void __launch_bounds__(256, 3) k_pair(
    const float* __restrict__ xc, const float* __restrict__ yc,
    const float* __restrict__ mu, const float* __restrict__ istd,
    const float* __restrict__ w1p, const float* __restrict__ b1p)
{
    __shared__ union { Tables t; Reduce r; } sm;   // 40960 B
    __shared__ float sy[ND];                        //  2048 B

    const int tile = blockIdx.x, k = blockIdx.y, b = blockIdx.z;
    const int tid = threadIdx.x;

    const float PI2   = 6.2831853071795864f;
    const float ALPHA = 5.3364454f;   // 2pi*sqrt(0.5*log2(e))

    // ---- build full c-table (two points per thread), y folded into cos/sin ----
    #pragma unroll
    for (int c = tid; c < ND; c += 256) {
        const float x0 = xc[((b * ND + c) * 2 + 0) * NCHv + k];
        const float x1 = xc[((b * ND + c) * 2 + 1) * NCHv + k];
        const float y  = yc[(b * ND + c) * NCHv + k];
        float U0[4], U1[4], CO[4], SI[4], P[4];
        #pragma unroll
        for (int m = 0; m < NMIXv; m++) {
            const float u0 = x0 * istd[2 * m + 0] * ALPHA;
            const float u1 = x1 * istd[2 * m + 1] * ALPHA;
            float t = fmaf(x0, mu[2 * m + 0], x1 * mu[2 * m + 1]);
            t -= rintf(t);
            float sn, cn; __sincosf(PI2 * t, &sn, &cn);
            U0[m] = u0; U1[m] = u1; CO[m] = cn * y; SI[m] = sn * y;
            P[m] = -fmaf(u0, u0, u1 * u1);
        }
        sm.t.A[c] = make_float4(U0[0], U0[1], U1[0], U1[1]);
        sm.t.B[c] = make_float4(CO[0], CO[1], SI[0], SI[1]);
        sm.t.C[c] = make_float4(U0[2], U0[3], U1[2], U1[3]);
        sm.t.D[c] = make_float4(CO[2], CO[3], SI[2], SI[3]);
        sm.t.P[c] = make_float4(P[0], P[1], P[2], P[3]);
        sy[c] = y;
    }

    // ---- per-lane A-side values (scalar registers) ----
    const int al = tid & 31;
    const int cs = tid >> 5;          // c-split 0..7, uniform per warp
    const int a  = tile * 32 + al;

    float a00, a01, a02, a03;   // 2*u0 per mix
    float a10, a11, a12, a13;   // 2*u1 per mix
    float ca0, ca1, ca2, ca3;   // cos per mix
    float sa0, sa1, sa2, sa3;   // sin per mix
    float pa0, pa1, pa2, pa3;   // -(|u|^2) per mix
    {
        const float x0 = xc[((b * ND + a) * 2 + 0) * NCHv + k];
        const float x1 = xc[((b * ND + a) * 2 + 1) * NCHv + k];
        float U0[4], U1[4], CO[4], SI[4], P[4];
        #pragma unroll
        for (int m = 0; m < NMIXv; m++) {
            const float u0 = x0 * istd[2 * m + 0] * ALPHA;
            const float u1 = x1 * istd[2 * m + 1] * ALPHA;
            float t = fmaf(x0, mu[2 * m + 0], x1 * mu[2 * m + 1]);
            t -= rintf(t);
            float sn, cn; __sincosf(PI2 * t, &sn, &cn);
            U0[m] = 2.0f * u0; U1[m] = 2.0f * u1; CO[m] = cn; SI[m] = sn;
            P[m] = -fmaf(u0, u0, u1 * u1);
        }
        a00 = U0[0]; a01 = U0[1]; a02 = U0[2]; a03 = U0[3];
        a10 = U1[0]; a11 = U1[1]; a12 = U1[2]; a13 = U1[3];
        ca0 = CO[0]; ca1 = CO[1]; ca2 = CO[2]; ca3 = CO[3];
        sa0 = SI[0]; sa1 = SI[1]; sa2 = SI[2]; sa3 = SI[3];
        pa0 = P[0];  pa1 = P[1];  pa2 = P[2];  pa3 = P[3];
    }
    __syncthreads();

    // ---- pair loop: warp = 32 a-lanes, 8 c-splits x 64 iters, scalar math ----
    float acc0 = 0.f, acc1 = 0.f, acc2 = 0.f, acc3 = 0.f;

    #pragma unroll 4
    for (int c = cs; c < ND; c += 8) {
        const float4 A = sm.t.A[c];
        const float4 B = sm.t.B[c];
        const float4 C = sm.t.C[c];
        const float4 D = sm.t.D[c];
        const float4 P = sm.t.P[c];
        // mix 0
        {
            float s = pa0 + P.x;
            s = fmaf(A.x, a00, s);
            s = fmaf(A.z, a10, s);
            const float cv = fmaf(B.x, ca0, B.z * sa0);
            acc0 = fmaf(ex2f(s), cv, acc0);
        }
        // mix 1
        {
            float s = pa1 + P.y;
            s = fmaf(A.y, a01, s);
            s = fmaf(A.w, a11, s);
            const float cv = fmaf(B.y, ca1, B.w * sa1);
            acc1 = fmaf(ex2f(s), cv, acc1);
        }
        // mix 2
        {
            float s = pa2 + P.z;
            s = fmaf(C.x, a02, s);
            s = fmaf(C.z, a12, s);
            const float cv = fmaf(D.x, ca2, D.z * sa2);
            acc2 = fmaf(ex2f(s), cv, acc2);
        }
        // mix 3
        {
            float s = pa3 + P.w;
            s = fmaf(C.y, a03, s);
            s = fmaf(C.w, a13, s);
            const float cv = fmaf(D.y, ca3, D.w * sa3);
            acc3 = fmaf(ex2f(s), cv, acc3);
        }
    }

    __syncthreads();   // tables dead; Reduce aliases them
    sm.r.red[cs][al][0] = acc0;
    sm.r.red[cs][al][1] = acc1;
    sm.r.red[cs][al][2] = acc2;
    sm.r.red[cs][al][3] = acc3;
    __syncthreads();

    // ---- reduce 8 c-splits, add zitter ----
    if (tid < 128) {
        const int lane = tid >> 2, m = tid & 3;
        float f = sm.r.red[0][lane][m];
        #pragma unroll
        for (int s = 1; s < 8; s++) f += sm.r.red[s][lane][m];
        f += 1.0e-4f * sy[tile * 32 + lane];
        sm.r.red[0][lane][m] = f;
    }
    __syncthreads();

    // ---- fused layer 1 on this tile's 32 a's ----
    {
        const int j = tid & 127, q = tid >> 7;   // q in {0,1}: 16 a's each
        const float wv0 = w1p[j * 5 + 0], wv1 = w1p[j * 5 + 1], wv2 = w1p[j * 5 + 2];
        const float wv3 = w1p[j * 5 + 3], wv4 = w1p[j * 5 + 4], bb = b1p[j];
        float acc = 0.f;
        #pragma unroll
        for (int aa = 0; aa < 16; aa++) {
            const int lane = q * 16 + aa;
            const float4 f = *(const float4*)&sm.r.red[0][lane][0];
            const float y = sy[tile * 32 + lane];
            float h = fmaf(wv0, f.x, bb);
            h = fmaf(wv1, f.y, h);
            h = fmaf(wv2, f.z, h);
            h = fmaf(wv3, f.w, h);
            h = fmaf(wv4, y, h);
            acc += fmaxf(h, 0.f);
        }
        sm.r.sred[q][j] = acc;
    }
    __syncthreads();
    if (tid < HD) {
        g_part[((b * NCHv + k) * NTILE + tile) * HD + tid] =
            sm.r.sred[0][tid] + sm.r.sred[1][tid];
    }
}

// ---------------- kernel 2: tile reduce + layers 2..5 -----------------
// grid 8 (batch), 512 threads
__global__ void __launch_bounds__(512) k_tail(
    const float* __restrict__ w2, const float* __restrict__ b2,
    const float* __restrict__ w3, const float* __restrict__ b3,
    const float* __restrict__ w4, const float* __restrict__ b4,
    const float* __restrict__ w5, const float* __restrict__ b5,
    float* __restrict__ out)
{
    __shared__ float sred[4][HD];
    __shared__ __align__(16) float h1[NCHv * HD];
    __shared__ __align__(16) float h2[HD];
    __shared__ __align__(16) float h3[HD];
    __shared__ float out5[NCHv * NMIXv][4];

    const int b = blockIdx.x, tid = threadIdx.x;
    const int j = tid & 127, q = tid >> 7;

    // reduce 16 tile-partials per (k,j) -> h1 (mean over 512 a)
    if (tid < NCHv * HD) {
        const int kk = tid >> 7, jj = tid & 127;
        const float* p = &g_part[((b * NCHv + kk) * NTILE) * HD + jj];
        float acc = 0.f;
        #pragma unroll
        for (int t = 0; t < NTILE; t++) acc += p[t * HD];
        h1[tid] = acc * (1.0f / 512.0f);
    }
    __syncthreads();

    // layer 2: 384 -> 128
    {
        float acc0 = 0.f, acc1 = 0.f;
        const float4* wr = (const float4*)(w2 + j * (NCHv * HD) + q * 96);
        const float4* xv = (const float4*)(h1 + q * 96);
        #pragma unroll 12
        for (int i = 0; i < 24; i += 2) {
            { const float4 w = wr[i], x = xv[i];
              acc0 = fmaf(w.x, x.x, acc0); acc0 = fmaf(w.y, x.y, acc0);
              acc0 = fmaf(w.z, x.z, acc0); acc0 = fmaf(w.w, x.w, acc0); }
            { const float4 w = wr[i+1], x = xv[i+1];
              acc1 = fmaf(w.x, x.x, acc1); acc1 = fmaf(w.y, x.y, acc1);
              acc1 = fmaf(w.z, x.z, acc1); acc1 = fmaf(w.w, x.w, acc1); }
        }
        sred[q][j] = acc0 + acc1;
        __syncthreads();
        if (tid < HD)
            h2[tid] = fmaxf(sred[0][tid] + sred[1][tid] + sred[2][tid] + sred[3][tid]
                            + b2[tid], 0.f);
        __syncthreads();
    }

    // layer 3: 128 -> 128
    {
        float acc0 = 0.f;
        const float4* wr = (const float4*)(w3 + j * HD + q * 32);
        const float4* xv = (const float4*)(h2 + q * 32);
        #pragma unroll
        for (int i = 0; i < 8; i++) {
            const float4 w = wr[i], x = xv[i];
            acc0 = fmaf(w.x, x.x, acc0); acc0 = fmaf(w.y, x.y, acc0);
            acc0 = fmaf(w.z, x.z, acc0); acc0 = fmaf(w.w, x.w, acc0);
        }
        sred[q][j] = acc0;
        __syncthreads();
        if (tid < HD)
            h3[tid] = fmaxf(sred[0][tid] + sred[1][tid] + sred[2][tid] + sred[3][tid]
                            + b3[tid], 0.f);
        __syncthreads();
    }

    // layer 4: 128 -> 128 (into h2)
    {
        float acc0 = 0.f;
        const float4* wr = (const float4*)(w4 + j * HD + q * 32);
        const float4* xv = (const float4*)(h3 + q * 32);
        #pragma unroll
        for (int i = 0; i < 8; i++) {
            const float4 w = wr[i], x = xv[i];
            acc0 = fmaf(w.x, x.x, acc0); acc0 = fmaf(w.y, x.y, acc0);
            acc0 = fmaf(w.z, x.z, acc0); acc0 = fmaf(w.w, x.w, acc0);
        }
        sred[q][j] = acc0;
        __syncthreads();
        if (tid < HD)
            h2[tid] = fmaxf(sred[0][tid] + sred[1][tid] + sred[2][tid] + sred[3][tid]
                            + b4[tid], 0.f);
        __syncthreads();
    }

    // layer 5: 128 -> 12
    if (tid < NCHv * NMIXv * 4) {
        const int j5 = tid >> 2, p = tid & 3;
        float acc = 0.f;
        const float4* wr = (const float4*)(w5 + j5 * HD + p * 32);
        const float4* xv = (const float4*)(h2 + p * 32);
        #pragma unroll
        for (int i = 0; i < 8; i++) {
            const float4 w = wr[i], x = xv[i];
            acc = fmaf(w.x, x.x, acc); acc = fmaf(w.y, x.y, acc);
            acc = fmaf(w.z, x.z, acc); acc = fmaf(w.w, x.w, acc);
        }
        out5[j5][p] = acc;
    }
    __syncthreads();
    if (tid < NCHv * NMIXv)
        out[b * (NCHv * NMIXv) + tid] =
            out5[tid][0] + out5[tid][1] + out5[tid][2] + out5[tid][3] + b5[tid];
}

// ---------------- launch ----------------
extern "C" void kernel_launch(void* const* d_in, const int* in_sizes, int n_in,
                              void* d_out, int out_size)
{
    const float* xc   = (const float*)d_in[0];
    const float* yc   = (const float*)d_in[1];
    const float* mu   = (const float*)d_in[2];
    const float* istd = (const float*)d_in[3];
    const float* w1   = (const float*)d_in[4];
    const float* b1   = (const float*)d_in[5];
    const float* w2   = (const float*)d_in[6];
    const float* b2   = (const float*)d_in[7];
    const float* w3   = (const float*)d_in[8];
    const float* b3   = (const float*)d_in[9];
    const float* w4   = (const float*)d_in[10];
    const float* b4   = (const float*)d_in[11];
    const float* w5   = (const float*)d_in[12];
    const float* b5   = (const float*)d_in[13];
    float* out = (float*)d_out;

    dim3 g1(NTILE, NCHv, NBv);   // 16 x 3 x 8 = 384 blocks, 256 threads
    k_pair<<<g1, 256>>>(xc, yc, mu, istd, w1, b1);
    k_tail<<<NBv, 512>>>(w2, b2, w3, b3, w4, b4, w5, b5, out);
}